// round 10
// baseline (speedup 1.0000x reference)
#include <cuda_runtime.h>
#include <cuda_bf16.h>

// MaxPool3d kernel=2 stride=2 over [B=2, C=32, D=128, H=128, W=128] fp32.
// Output [2, 32, 64, 64, 64]. Pure HBM stream: 512 MiB read + 64 MiB write.
//
// R7: finest granularity — 1 output per thread.
// Granularity trend: 8 out/thr = 96.4us, 4 out/thr = 88.8us, 2 out/thr = 86.5us.
//  - 4 independent LDG.64 per thread (one float2 per (d,h) window row)
//  - 1 STG.32 per thread (128 B/warp contiguous)
//  - per-warp per-row footprint: 256 B contiguous, perfectly coalesced
//  - ~20 regs -> full occupancy; shallowest per-thread L1tex queue
//  - 16,777,216 threads = 65536 blocks x 256, exact fit
//  - __ldcs/__stcs evict-first streaming

#define IN_W 128
#define IN_HW (128 * 128)
#define IN_DHW (128 * 128 * 128)
#define OUT_W 64
#define OUT_HW (64 * 64)
#define OUT_DHW (64 * 64 * 64)

__global__ __launch_bounds__(256) void maxpool3d_k2s2_kernel(
    const float* __restrict__ in, float* __restrict__ out)
{
    int t = blockIdx.x * 256 + threadIdx.x;   // 0 .. 16,777,215 (exact fit)

    int w  = t & 63;                 // out w
    int h  = (t >> 6) & 63;          // out h
    int d  = (t >> 12) & 63;         // out d
    int bc = t >> 18;                // plane (b*C + c), 0..63

    // 2 input floats per row starting at iw = 2w.
    const float2* base = (const float2*)(in
        + (size_t)bc * IN_DHW
        + (size_t)(d << 1) * IN_HW
        + (size_t)(h << 1) * IN_W
        + (w << 1));

    // Offsets in float2 units: +64 = next h row (128 floats),
    // +8192 = next d slab (16384 floats).
    float2 a = __ldcs(base + 0);
    float2 b = __ldcs(base + 64);
    float2 c = __ldcs(base + 8192);
    float2 e = __ldcs(base + 8256);

    float m = fmaxf(fmaxf(fmaxf(a.x, a.y), fmaxf(b.x, b.y)),
                    fmaxf(fmaxf(c.x, c.y), fmaxf(e.x, e.y)));

    float* op = out
        + (size_t)bc * OUT_DHW
        + (size_t)d * OUT_HW
        + (size_t)h * OUT_W
        + w;
    __stcs(op, m);
}

extern "C" void kernel_launch(void* const* d_in, const int* in_sizes, int n_in,
                              void* d_out, int out_size)
{
    const float* in = (const float*)d_in[0];
    float* out = (float*)d_out;

    // out_size = 16,777,216 outputs -> 1 per thread -> 65536 blocks x 256
    int blocks = out_size / 256;
    maxpool3d_k2s2_kernel<<<blocks, 256>>>(in, out);
}